// round 11
// baseline (speedup 1.0000x reference)
#include <cuda_runtime.h>

#define NN 8192
#define INDIM 512
#define HID 50
#define ZD 128
#define NCAT 64
#define EPSV 1e-8f
#define NWORK_MAX (NN/32 + NCAT)
#define NFX (NN/32)
#define NFZ (NN/32)

typedef unsigned long long u64;

// ---------------- scratch ----------------------------------------------------
__device__ float g_fx[NN*ZD];    // natural order
__device__ float g_fz[NN*ZD];    // natural order
__device__ float g_Tg[NN];       // T, sorted order
__device__ float g_part[NWORK_MAX*64];  // per-work partial sums [work][half*32+row]
__device__ int   g_done[NWORK_MAX];
__device__ int   g_cnt[NCAT], g_start[NCAT];
__device__ int   g_sorted[NN];
__device__ int   g_work[NWORK_MAX];
__device__ int   g_nwork;

// ---------------- f32x2 helpers ----------------------------------------------
__device__ __forceinline__ u64 dup2(float x){
    u64 r; asm("mov.b64 %0, {%1, %1};" : "=l"(r) : "f"(x)); return r;
}
__device__ __forceinline__ void fma2(u64 &d, u64 a, u64 b){
    asm("fma.rn.f32x2 %0, %1, %2, %0;" : "+l"(d) : "l"(a), "l"(b));
}
__device__ __forceinline__ float2 unpk(u64 v){
    float2 f; asm("mov.b64 {%0, %1}, %2;" : "=f"(f.x), "=f"(f.y) : "l"(v)); return f;
}
__device__ __forceinline__ float softplusf(float v){
    return fmaxf(v, 0.f) + log1pf(__expf(-fabsf(v)));
}

// ---------------- prep: block0 = bucket+reset, blocks 1..512 = fx/fz ---------
__global__ void prep_kernel(const float* __restrict__ x,  const float* __restrict__ W1,
                            const float* __restrict__ b1, const float* __restrict__ W2,
                            const float* __restrict__ b2, const float* __restrict__ z,
                            const float* __restrict__ Wz, const float* __restrict__ bz,
                            const int*   __restrict__ c){
    __shared__ __align__(16) float sbuf[8064];
    __shared__ float aux128[128];
    __shared__ float aux64[64];
    __shared__ int   s_cnt[NCAT];
    __shared__ int   s_cursor[NCAT];
    int tid  = threadIdx.x;
    int lane = tid & 31;

    if (blockIdx.x == 0){
        // ================= bucket sort (warp-aggregated atomics) =============
        if (tid < NCAT) s_cnt[tid] = 0;
        for (int i = tid; i < NWORK_MAX; i += 256) g_done[i] = 0;   // reset tickets
        __syncthreads();
        for (int i = tid; i < NN; i += 256){
            int cc = min(max(c[i], 0), NCAT - 1);
            unsigned m = __match_any_sync(0xffffffffu, cc);
            if ((m & ((1u << lane) - 1)) == 0) atomicAdd(&s_cnt[cc], __popc(m));
        }
        __syncthreads();
        if (tid == 0){
            int s = 0, w = 0;
            for (int cc = 0; cc < NCAT; cc++){
                s_cursor[cc] = s;
                g_start[cc]  = s;
                int n = s_cnt[cc];
                g_cnt[cc] = n;
                s += n;
                int nt = (n + 31) >> 5;
                for (int t = 0; t < nt; t++) g_work[w++] = (cc << 16) | t;
            }
            g_nwork = w;
        }
        __syncthreads();
        for (int i = tid; i < NN; i += 256){
            int cc = min(max(c[i], 0), NCAT - 1);
            unsigned m = __match_any_sync(0xffffffffu, cc);
            int leader = __ffs(m) - 1;
            int rank   = __popc(m & ((1u << lane) - 1));
            int base   = 0;
            if (lane == leader) base = atomicAdd(&s_cursor[cc], __popc(m));
            base = __shfl_sync(0xffffffffu, base, leader);
            g_sorted[base + rank] = i;
        }
    } else if (blockIdx.x <= NFX){
        // ================= fx = relu(x@W1+b1)@W2+b2, 32 rows =================
        float* As  = sbuf;            // [32][36]
        float* Bs  = sbuf + 1152;     // [32][64]
        float* Hs  = sbuf;            // [32][52]
        float* W2s = sbuf + 1664;     // [50][128]
        float* b1s = aux64;
        float* b2s = aux128;

        int row0 = (blockIdx.x - 1) * 32;
        if (tid < 64)  b1s[tid] = (tid < HID) ? b1[tid] : 0.f;
        if (tid < 128) b2s[tid] = b2[tid];

        float4 w2r[7];
        #pragma unroll
        for (int i = 0; i < 7; i++){
            int q = tid + 256*i;
            if (q < 1600) w2r[i] = *(const float4*)&W2[q*4];
        }

        int ar = tid >> 3, ac4 = tid & 7;
        float4 pa = *(const float4*)&x[(size_t)(row0 + ar)*INDIM + ac4*4];
        float pb[8];
        #pragma unroll
        for (int i = 0; i < 8; i++){
            int e = tid + 256*i;
            int k = e >> 6, j = e & 63;
            pb[i] = (j < HID) ? W1[(size_t)k*HID + j] : 0.f;
        }

        int rg = (tid >> 4) * 2;
        int cg = (tid & 15) * 4;
        u64 acc2[2][2] = {};

        for (int t = 0; t < 16; t++){
            __syncthreads();
            *(float4*)&As[ar*36 + ac4*4] = pa;
            #pragma unroll
            for (int i = 0; i < 8; i++){
                int e = tid + 256*i;
                Bs[(e >> 6)*64 + (e & 63)] = pb[i];
            }
            __syncthreads();
            if (t < 15){
                int k0 = (t+1)*32;
                pa = *(const float4*)&x[(size_t)(row0 + ar)*INDIM + k0 + ac4*4];
                #pragma unroll
                for (int i = 0; i < 8; i++){
                    int e = tid + 256*i;
                    int k = e >> 6, j = e & 63;
                    pb[i] = (j < HID) ? W1[(size_t)(k0 + k)*HID + j] : 0.f;
                }
            }
            #pragma unroll
            for (int k = 0; k < 32; k++){
                u64 da0 = dup2(As[rg*36 + k]);
                u64 da1 = dup2(As[(rg+1)*36 + k]);
                ulonglong2 bb = *(const ulonglong2*)&Bs[k*64 + cg];
                fma2(acc2[0][0], da0, bb.x); fma2(acc2[0][1], da0, bb.y);
                fma2(acc2[1][0], da1, bb.x); fma2(acc2[1][1], da1, bb.y);
            }
        }
        __syncthreads();

        #pragma unroll
        for (int i = 0; i < 2; i++){
            float2 p0 = unpk(acc2[i][0]);
            float2 p1 = unpk(acc2[i][1]);
            float hv[4] = {p0.x, p0.y, p1.x, p1.y};
            #pragma unroll
            for (int j = 0; j < 4; j++){
                int cc = cg + j;
                if (cc < HID) Hs[(rg+i)*52 + cc] = fmaxf(hv[j] + b1s[cc], 0.f);
            }
        }
        #pragma unroll
        for (int i = 0; i < 7; i++){
            int q = tid + 256*i;
            if (q < 1600) *(float4*)&W2s[q*4] = w2r[i];
        }
        __syncthreads();

        {
            int r0 = (tid >> 5) * 4;
            int c0 = (tid & 31) * 4;
            u64 a2[4][2] = {};
            #pragma unroll
            for (int k = 0; k < HID; k++){
                ulonglong2 bb = *(const ulonglong2*)&W2s[k*128 + c0];
                #pragma unroll
                for (int i = 0; i < 4; i++){
                    u64 da = dup2(Hs[(r0+i)*52 + k]);
                    fma2(a2[i][0], da, bb.x);
                    fma2(a2[i][1], da, bb.y);
                }
            }
            #pragma unroll
            for (int i = 0; i < 4; i++){
                float2 p0 = unpk(a2[i][0]);
                float2 p1 = unpk(a2[i][1]);
                float4 v = make_float4(p0.x + b2s[c0], p0.y + b2s[c0+1],
                                       p1.x + b2s[c0+2], p1.y + b2s[c0+3]);
                *(float4*)&g_fx[(size_t)(row0 + r0 + i)*ZD + c0] = v;
            }
        }
    } else {
        // ================= fz = z@Wz+bz, 32 rows =============================
        float* Zs  = sbuf;            // [32][36]
        float* Wzt = sbuf + 1152;     // [32][132]
        float* bzs = aux128;

        int row0 = (blockIdx.x - 1 - NFX) * 32;
        if (tid < 128) bzs[tid] = bz[tid];

        int ar = tid >> 3, ac4 = tid & 7;
        float4 pz = *(const float4*)&z[(size_t)(row0 + ar)*ZD + ac4*4];
        float4 pw[4];
        #pragma unroll
        for (int i = 0; i < 4; i++){
            int q = tid + 256*i;
            pw[i] = *(const float4*)&Wz[(size_t)(q >> 5)*ZD + (q & 31)*4];
        }

        int rg = (tid >> 4) * 2;
        int cg = (tid & 15) * 4;
        u64 acc2[2][4] = {};

        for (int kt = 0; kt < 4; kt++){
            __syncthreads();
            *(float4*)&Zs[ar*36 + ac4*4] = pz;
            #pragma unroll
            for (int i = 0; i < 4; i++){
                int q = tid + 256*i;
                *(float4*)&Wzt[(q >> 5)*132 + (q & 31)*4] = pw[i];
            }
            __syncthreads();
            if (kt < 3){
                int k0 = (kt+1)*32;
                pz = *(const float4*)&z[(size_t)(row0 + ar)*ZD + k0 + ac4*4];
                #pragma unroll
                for (int i = 0; i < 4; i++){
                    int q = tid + 256*i;
                    pw[i] = *(const float4*)&Wz[(size_t)(k0 + (q >> 5))*ZD + (q & 31)*4];
                }
            }
            #pragma unroll
            for (int k = 0; k < 32; k++){
                u64 da0 = dup2(Zs[rg*36 + k]);
                u64 da1 = dup2(Zs[(rg+1)*36 + k]);
                ulonglong2 b0 = *(const ulonglong2*)&Wzt[k*132 + cg];
                ulonglong2 b1 = *(const ulonglong2*)&Wzt[k*132 + cg + 64];
                fma2(acc2[0][0], da0, b0.x); fma2(acc2[0][1], da0, b0.y);
                fma2(acc2[0][2], da0, b1.x); fma2(acc2[0][3], da0, b1.y);
                fma2(acc2[1][0], da1, b0.x); fma2(acc2[1][1], da1, b0.y);
                fma2(acc2[1][2], da1, b1.x); fma2(acc2[1][3], da1, b1.y);
            }
        }

        #pragma unroll
        for (int i = 0; i < 2; i++){
            size_t base = (size_t)(row0 + rg + i)*ZD;
            float2 p0 = unpk(acc2[i][0]), p1 = unpk(acc2[i][1]);
            float2 p2 = unpk(acc2[i][2]), p3 = unpk(acc2[i][3]);
            *(float4*)&g_fz[base + cg] =
                make_float4(p0.x + bzs[cg],   p0.y + bzs[cg+1],
                            p1.x + bzs[cg+2], p1.y + bzs[cg+3]);
            *(float4*)&g_fz[base + cg + 64] =
                make_float4(p2.x + bzs[cg+64], p2.y + bzs[cg+65],
                            p3.x + bzs[cg+66], p3.y + bzs[cg+67]);
        }
    }
}

// ---------------- fused u + neg, j-split: 2 blocks per work item -------------
// phase1: FxsT = sbuf[0..4608) pitch36 [k][r]; Wst = sbuf[4608..8832) pitch132
// phase2: Us = sbuf[0..4224) pitch132;  Fs = sbuf[4224..8448) pitch132
__global__ void uneg_kernel(const float* __restrict__ Ws, float* __restrict__ out){
    __shared__ __align__(16) float sbuf[8832];
    __shared__ int   gidx[32];
    __shared__ int   s_flag;
    float* FxsT = sbuf;
    float* Wst  = sbuf + 4608;
    float* Us   = sbuf;
    float* Fs   = sbuf + 4224;

    int w2   = blockIdx.x >> 1;
    int half = blockIdx.x & 1;
    if (w2 >= g_nwork) return;
    int item  = g_work[w2];
    int cat   = item >> 16, tile = item & 0xffff;
    int start = g_start[cat], cnt = g_cnt[cat];
    int i0    = tile * 32;
    int ni    = min(32, cnt - i0);
    int tid   = threadIdx.x;

    int nt  = (cnt + 31) >> 5;
    int h0  = (nt + 1) >> 1;
    int jtb = half ? h0 : 0;
    int jte = half ? nt : h0;

    if (tid < 32) gidx[tid] = (tid < ni) ? g_sorted[start + i0 + tid] : 0;

    // stage fx tile transposed (gather rows via g_sorted)
    {
        int r = tid & 31;
        int gi = 0; bool act = (r < ni);
        if (act) gi = g_sorted[start + i0 + r];
        #pragma unroll
        for (int i = 0; i < 4; i++){
            int k4 = (tid >> 5) + 8*i;
            float4 v = make_float4(0.f,0.f,0.f,0.f);
            if (act) v = *(const float4*)&g_fx[(size_t)gi*ZD + k4*4];
            FxsT[(k4*4+0)*36 + r] = v.x;
            FxsT[(k4*4+1)*36 + r] = v.y;
            FxsT[(k4*4+2)*36 + r] = v.z;
            FxsT[(k4*4+3)*36 + r] = v.w;
        }
    }

    const float* Wc = Ws + (size_t)cat*ZD*ZD;
    float4 pw[4];
    #pragma unroll
    for (int i = 0; i < 4; i++){
        int q = tid + 256*i;
        pw[i] = *(const float4*)&Wc[(size_t)(q >> 5)*ZD + (q & 31)*4];
    }
    // prefetch first Fs tile of this half's j-range (gathered)
    float4 pf[4];
    if (jtb < jte){
        int j0 = jtb*32;
        int nj0 = min(32, cnt - j0);
        #pragma unroll
        for (int i = 0; i < 4; i++){
            int q = tid + 256*i;
            int r = q >> 5;
            pf[i] = make_float4(0.f,0.f,0.f,0.f);
            if (r < nj0){
                int gj = g_sorted[start + j0 + r];
                pf[i] = *(const float4*)&g_fz[(size_t)gj*ZD + (q & 31)*4];
            }
        }
    }

    int r0 = (tid >> 5) * 4;     // warp-uniform row group
    int c0 = (tid & 31) * 4;
    u64 acc2[4][2] = {};

    for (int kt = 0; kt < ZD; kt += 32){
        __syncthreads();
        #pragma unroll
        for (int i = 0; i < 4; i++){
            int q = tid + 256*i;
            *(float4*)&Wst[(q >> 5)*132 + (q & 31)*4] = pw[i];
        }
        __syncthreads();
        if (kt < ZD - 32){
            #pragma unroll
            for (int i = 0; i < 4; i++){
                int q = tid + 256*i;
                pw[i] = *(const float4*)&Wc[(size_t)(kt + 32 + (q >> 5))*ZD + (q & 31)*4];
            }
        }
        #pragma unroll
        for (int k = 0; k < 32; k++){
            ulonglong2 av = *(const ulonglong2*)&FxsT[(kt+k)*36 + r0];
            float4 bv = *(const float4*)&Wst[k*132 + c0];
            u64 d0 = dup2(bv.x), d1 = dup2(bv.y), d2 = dup2(bv.z), d3 = dup2(bv.w);
            fma2(acc2[0][0], av.x, d0); fma2(acc2[0][1], av.y, d0);
            fma2(acc2[1][0], av.x, d1); fma2(acc2[1][1], av.y, d1);
            fma2(acc2[2][0], av.x, d2); fma2(acc2[2][1], av.y, d2);
            fma2(acc2[3][0], av.x, d3); fma2(acc2[3][1], av.y, d3);
        }
    }
    __syncthreads();

    {
        float2 q00 = unpk(acc2[0][0]), q10 = unpk(acc2[1][0]),
               q20 = unpk(acc2[2][0]), q30 = unpk(acc2[3][0]);
        float2 q01 = unpk(acc2[0][1]), q11 = unpk(acc2[1][1]),
               q21 = unpk(acc2[2][1]), q31 = unpk(acc2[3][1]);
        *(float4*)&Us[(r0+0)*132 + c0] = make_float4(q00.x, q10.x, q20.x, q30.x);
        *(float4*)&Us[(r0+1)*132 + c0] = make_float4(q00.y, q10.y, q20.y, q30.y);
        *(float4*)&Us[(r0+2)*132 + c0] = make_float4(q01.x, q11.x, q21.x, q31.x);
        *(float4*)&Us[(r0+3)*132 + c0] = make_float4(q01.y, q11.y, q21.y, q31.y);
    }

    int jj = tid & 31;
    int ig = tid >> 5;
    float sum[4] = {0.f, 0.f, 0.f, 0.f};

    for (int jt = jtb; jt < jte; jt++){
        int j0 = jt*32;
        int nj = min(32, cnt - j0);
        __syncthreads();
        #pragma unroll
        for (int i = 0; i < 4; i++){
            int q = tid + 256*i;
            *(float4*)&Fs[(q >> 5)*132 + (q & 31)*4] = pf[i];
        }
        __syncthreads();
        if (jt + 1 < jte){
            int j0n = j0 + 32;
            int njn = min(32, cnt - j0n);
            #pragma unroll
            for (int i = 0; i < 4; i++){
                int q = tid + 256*i;
                int r = q >> 5;
                pf[i] = make_float4(0.f,0.f,0.f,0.f);
                if (r < njn){
                    int gj = g_sorted[start + j0n + r];
                    pf[i] = *(const float4*)&g_fz[(size_t)gj*ZD + (q & 31)*4];
                }
            }
        }

        u64 a4[4] = {};
        #pragma unroll
        for (int k0 = 0; k0 < ZD; k0 += 4){
            ulonglong2 f = *(const ulonglong2*)&Fs[jj*132 + k0];
            #pragma unroll
            for (int m = 0; m < 4; m++){
                ulonglong2 u = *(const ulonglong2*)&Us[(ig*4 + m)*132 + k0];
                fma2(a4[m], u.x, f.x);
                fma2(a4[m], u.y, f.y);
            }
        }
        #pragma unroll
        for (int m = 0; m < 4; m++){
            float2 s = unpk(a4[m]);
            float d = s.x + s.y;
            int rr = ig*4 + m;
            if (jt == tile && jj == rr && rr < ni)
                g_Tg[start + i0 + rr] = softplusf(d);           // diagonal = T
            float v = (jj < nj) ? softplusf(d) : 0.f;
            v += __shfl_xor_sync(0xffffffffu, v, 16);
            v += __shfl_xor_sync(0xffffffffu, v, 8);
            v += __shfl_xor_sync(0xffffffffu, v, 4);
            v += __shfl_xor_sync(0xffffffffu, v, 2);
            v += __shfl_xor_sync(0xffffffffu, v, 1);
            sum[m] += v;
        }
    }

    // publish partials, ticket, last block finalizes
    if (jj == 0){
        #pragma unroll
        for (int m = 0; m < 4; m++)
            g_part[w2*64 + half*32 + ig*4 + m] = sum[m];
    }
    __threadfence();
    __syncthreads();
    if (tid == 0) s_flag = (atomicAdd(&g_done[w2], 1) == 1);
    __syncthreads();
    if (s_flag){
        __threadfence();
        if (tid < ni){
            float s = g_part[w2*64 + tid] + g_part[w2*64 + 32 + tid];
            float inv = 1.f / (float)cnt;
            out[gidx[tid]] = logf(g_Tg[start + i0 + tid] + EPSV) - logf(s*inv + EPSV);
        }
    }
}

// ---------------- launch ----------------------------------------------------
extern "C" void kernel_launch(void* const* d_in, const int* in_sizes, int n_in,
                              void* d_out, int out_size){
    const float* x  = (const float*)d_in[0];
    const int*   c  = (const int*)  d_in[1];
    const float* z  = (const float*)d_in[2];
    const float* W1 = (const float*)d_in[3];
    const float* b1 = (const float*)d_in[4];
    const float* W2 = (const float*)d_in[5];
    const float* b2 = (const float*)d_in[6];
    const float* Wz = (const float*)d_in[7];
    const float* bz = (const float*)d_in[8];
    const float* Ws = (const float*)d_in[9];
    float* out = (float*)d_out;

    prep_kernel <<<1 + NFX + NFZ, 256>>>(x, W1, b1, W2, b2, z, Wz, bz, c);
    uneg_kernel <<<2*NWORK_MAX, 256>>>(Ws, out);
}

// round 12
// speedup vs baseline: 1.3297x; 1.3297x over previous
#include <cuda_runtime.h>

#define NN 8192
#define INDIM 512
#define HID 50
#define ZD 128
#define NCAT 64
#define EPSV 1e-8f
#define NWORK_MAX (NN/32 + NCAT)
#define NFX (NN/32)
#define NFZ (NN/32)

// uneg dynamic smem layout (floats):
//  phase1: FxsTd [128][68] = 8704   | Wst [32][132] = 4224   (total 12928)
//  phase2: Us    [32][128] = 4096   | Fs  [64][132] = 8448   (total 12544)
#define UNEG_SMEM_FLOATS 12928
#define UNEG_SMEM_BYTES  (UNEG_SMEM_FLOATS*4)

typedef unsigned long long u64;

// ---------------- scratch ----------------------------------------------------
__device__ float g_fx[NN*ZD];    // natural order
__device__ float g_fz[NN*ZD];    // natural order
__device__ int   g_cnt[NCAT], g_start[NCAT];
__device__ int   g_sorted[NN];
__device__ int   g_work[NWORK_MAX];
__device__ int   g_nwork;

// ---------------- f32x2 helpers ----------------------------------------------
__device__ __forceinline__ u64 dup2(float x){
    u64 r; asm("mov.b64 %0, {%1, %1};" : "=l"(r) : "f"(x)); return r;
}
__device__ __forceinline__ void fma2(u64 &d, u64 a, u64 b){
    asm("fma.rn.f32x2 %0, %1, %2, %0;" : "+l"(d) : "l"(a), "l"(b));
}
__device__ __forceinline__ float2 unpk(u64 v){
    float2 f; asm("mov.b64 {%0, %1}, %2;" : "=f"(f.x), "=f"(f.y) : "l"(v)); return f;
}
__device__ __forceinline__ float softplusf(float v){
    return fmaxf(v, 0.f) + log1pf(__expf(-fabsf(v)));
}

// ---------------- prep: block0 = bucket, blocks 1..512 = fx/fz GEMMs ---------
__global__ void prep_kernel(const float* __restrict__ x,  const float* __restrict__ W1,
                            const float* __restrict__ b1, const float* __restrict__ W2,
                            const float* __restrict__ b2, const float* __restrict__ z,
                            const float* __restrict__ Wz, const float* __restrict__ bz,
                            const int*   __restrict__ c){
    __shared__ __align__(16) float sbuf[8064];
    __shared__ float aux128[128];
    __shared__ float aux64[64];
    __shared__ int   s_cnt[NCAT];
    __shared__ int   s_cursor[NCAT];
    int tid  = threadIdx.x;
    int lane = tid & 31;

    if (blockIdx.x == 0){
        // ================= bucket sort (warp-aggregated atomics) =============
        if (tid < NCAT) s_cnt[tid] = 0;
        __syncthreads();
        for (int i = tid; i < NN; i += 256){
            int cc = min(max(c[i], 0), NCAT - 1);
            unsigned m = __match_any_sync(0xffffffffu, cc);
            if ((m & ((1u << lane) - 1)) == 0) atomicAdd(&s_cnt[cc], __popc(m));
        }
        __syncthreads();
        if (tid == 0){
            int s = 0, w = 0;
            for (int cc = 0; cc < NCAT; cc++){
                s_cursor[cc] = s;
                g_start[cc]  = s;
                int n = s_cnt[cc];
                g_cnt[cc] = n;
                s += n;
                int nt = (n + 31) >> 5;
                for (int t = 0; t < nt; t++) g_work[w++] = (cc << 16) | t;
            }
            g_nwork = w;
        }
        __syncthreads();
        for (int i = tid; i < NN; i += 256){
            int cc = min(max(c[i], 0), NCAT - 1);
            unsigned m = __match_any_sync(0xffffffffu, cc);
            int leader = __ffs(m) - 1;
            int rank   = __popc(m & ((1u << lane) - 1));
            int base   = 0;
            if (lane == leader) base = atomicAdd(&s_cursor[cc], __popc(m));
            base = __shfl_sync(0xffffffffu, base, leader);
            g_sorted[base + rank] = i;
        }
    } else if (blockIdx.x <= NFX){
        // ================= fx = relu(x@W1+b1)@W2+b2, 32 rows =================
        float* As  = sbuf;            // [32][36]
        float* Bs  = sbuf + 1152;     // [32][64]
        float* Hs  = sbuf;            // [32][52]
        float* W2s = sbuf + 1664;     // [50][128]
        float* b1s = aux64;
        float* b2s = aux128;

        int row0 = (blockIdx.x - 1) * 32;
        if (tid < 64)  b1s[tid] = (tid < HID) ? b1[tid] : 0.f;
        if (tid < 128) b2s[tid] = b2[tid];

        float4 w2r[7];
        #pragma unroll
        for (int i = 0; i < 7; i++){
            int q = tid + 256*i;
            if (q < 1600) w2r[i] = *(const float4*)&W2[q*4];
        }

        int ar = tid >> 3, ac4 = tid & 7;
        float4 pa = *(const float4*)&x[(size_t)(row0 + ar)*INDIM + ac4*4];
        float pb[8];
        #pragma unroll
        for (int i = 0; i < 8; i++){
            int e = tid + 256*i;
            int k = e >> 6, j = e & 63;
            pb[i] = (j < HID) ? W1[(size_t)k*HID + j] : 0.f;
        }

        int rg = (tid >> 4) * 2;
        int cg = (tid & 15) * 4;
        u64 acc2[2][2] = {};

        for (int t = 0; t < 16; t++){
            __syncthreads();
            *(float4*)&As[ar*36 + ac4*4] = pa;
            #pragma unroll
            for (int i = 0; i < 8; i++){
                int e = tid + 256*i;
                Bs[(e >> 6)*64 + (e & 63)] = pb[i];
            }
            __syncthreads();
            if (t < 15){
                int k0 = (t+1)*32;
                pa = *(const float4*)&x[(size_t)(row0 + ar)*INDIM + k0 + ac4*4];
                #pragma unroll
                for (int i = 0; i < 8; i++){
                    int e = tid + 256*i;
                    int k = e >> 6, j = e & 63;
                    pb[i] = (j < HID) ? W1[(size_t)(k0 + k)*HID + j] : 0.f;
                }
            }
            #pragma unroll
            for (int k = 0; k < 32; k++){
                u64 da0 = dup2(As[rg*36 + k]);
                u64 da1 = dup2(As[(rg+1)*36 + k]);
                ulonglong2 bb = *(const ulonglong2*)&Bs[k*64 + cg];
                fma2(acc2[0][0], da0, bb.x); fma2(acc2[0][1], da0, bb.y);
                fma2(acc2[1][0], da1, bb.x); fma2(acc2[1][1], da1, bb.y);
            }
        }
        __syncthreads();

        #pragma unroll
        for (int i = 0; i < 2; i++){
            float2 p0 = unpk(acc2[i][0]);
            float2 p1 = unpk(acc2[i][1]);
            float hv[4] = {p0.x, p0.y, p1.x, p1.y};
            #pragma unroll
            for (int j = 0; j < 4; j++){
                int cc = cg + j;
                if (cc < HID) Hs[(rg+i)*52 + cc] = fmaxf(hv[j] + b1s[cc], 0.f);
            }
        }
        #pragma unroll
        for (int i = 0; i < 7; i++){
            int q = tid + 256*i;
            if (q < 1600) *(float4*)&W2s[q*4] = w2r[i];
        }
        __syncthreads();

        {
            int r0 = (tid >> 5) * 4;
            int c0 = (tid & 31) * 4;
            u64 a2[4][2] = {};
            #pragma unroll
            for (int k = 0; k < HID; k++){
                ulonglong2 bb = *(const ulonglong2*)&W2s[k*128 + c0];
                #pragma unroll
                for (int i = 0; i < 4; i++){
                    u64 da = dup2(Hs[(r0+i)*52 + k]);
                    fma2(a2[i][0], da, bb.x);
                    fma2(a2[i][1], da, bb.y);
                }
            }
            #pragma unroll
            for (int i = 0; i < 4; i++){
                float2 p0 = unpk(a2[i][0]);
                float2 p1 = unpk(a2[i][1]);
                float4 v = make_float4(p0.x + b2s[c0], p0.y + b2s[c0+1],
                                       p1.x + b2s[c0+2], p1.y + b2s[c0+3]);
                *(float4*)&g_fx[(size_t)(row0 + r0 + i)*ZD + c0] = v;
            }
        }
    } else {
        // ================= fz = z@Wz+bz, 32 rows =============================
        float* Zs  = sbuf;            // [32][36]
        float* Wzt = sbuf + 1152;     // [32][132]
        float* bzs = aux128;

        int row0 = (blockIdx.x - 1 - NFX) * 32;
        if (tid < 128) bzs[tid] = bz[tid];

        int ar = tid >> 3, ac4 = tid & 7;
        float4 pz = *(const float4*)&z[(size_t)(row0 + ar)*ZD + ac4*4];
        float4 pw[4];
        #pragma unroll
        for (int i = 0; i < 4; i++){
            int q = tid + 256*i;
            pw[i] = *(const float4*)&Wz[(size_t)(q >> 5)*ZD + (q & 31)*4];
        }

        int rg = (tid >> 4) * 2;
        int cg = (tid & 15) * 4;
        u64 acc2[2][4] = {};

        for (int kt = 0; kt < 4; kt++){
            __syncthreads();
            *(float4*)&Zs[ar*36 + ac4*4] = pz;
            #pragma unroll
            for (int i = 0; i < 4; i++){
                int q = tid + 256*i;
                *(float4*)&Wzt[(q >> 5)*132 + (q & 31)*4] = pw[i];
            }
            __syncthreads();
            if (kt < 3){
                int k0 = (kt+1)*32;
                pz = *(const float4*)&z[(size_t)(row0 + ar)*ZD + k0 + ac4*4];
                #pragma unroll
                for (int i = 0; i < 4; i++){
                    int q = tid + 256*i;
                    pw[i] = *(const float4*)&Wz[(size_t)(k0 + (q >> 5))*ZD + (q & 31)*4];
                }
            }
            #pragma unroll
            for (int k = 0; k < 32; k++){
                u64 da0 = dup2(Zs[rg*36 + k]);
                u64 da1 = dup2(Zs[(rg+1)*36 + k]);
                ulonglong2 b0 = *(const ulonglong2*)&Wzt[k*132 + cg];
                ulonglong2 b1 = *(const ulonglong2*)&Wzt[k*132 + cg + 64];
                fma2(acc2[0][0], da0, b0.x); fma2(acc2[0][1], da0, b0.y);
                fma2(acc2[0][2], da0, b1.x); fma2(acc2[0][3], da0, b1.y);
                fma2(acc2[1][0], da1, b0.x); fma2(acc2[1][1], da1, b0.y);
                fma2(acc2[1][2], da1, b1.x); fma2(acc2[1][3], da1, b1.y);
            }
        }

        #pragma unroll
        for (int i = 0; i < 2; i++){
            size_t base = (size_t)(row0 + rg + i)*ZD;
            float2 p0 = unpk(acc2[i][0]), p1 = unpk(acc2[i][1]);
            float2 p2 = unpk(acc2[i][2]), p3 = unpk(acc2[i][3]);
            *(float4*)&g_fz[base + cg] =
                make_float4(p0.x + bzs[cg],   p0.y + bzs[cg+1],
                            p1.x + bzs[cg+2], p1.y + bzs[cg+3]);
            *(float4*)&g_fz[base + cg + 64] =
                make_float4(p2.x + bzs[cg+64], p2.y + bzs[cg+65],
                            p3.x + bzs[cg+66], p3.y + bzs[cg+67]);
        }
    }
}

// ---------------- fused u + neg + output, 32-row i-tiles ---------------------
// phase1: dup-A layout FxsTd[k][2r] (pitch 68), Wst[32][132]
// phase2: Us[32][128], Fs 64-row j-tiles [64][132]
__global__ void __launch_bounds__(256)
uneg_kernel(const float* __restrict__ Ws, float* __restrict__ out){
    extern __shared__ __align__(16) float dyn[];
    __shared__ float Ts[32];
    __shared__ int   gidx[32];
    float* FxsTd = dyn;          // [128][68]
    float* Wst   = dyn + 8704;   // [32][132]
    float* Us    = dyn;          // [32][128]
    float* Fs    = dyn + 4096;   // [64][132]

    int w = blockIdx.x;
    if (w >= g_nwork) return;
    int item  = g_work[w];
    int cat   = item >> 16, tile = item & 0xffff;
    int start = g_start[cat], cnt = g_cnt[cat];
    int i0    = tile * 32;
    int ni    = min(32, cnt - i0);
    int tid   = threadIdx.x;

    if (tid < 32) gidx[tid] = (tid < ni) ? g_sorted[start + i0 + tid] : 0;

    // stage fx tile transposed + DUPLICATED: FxsTd[k][2r] = FxsTd[k][2r+1] = fx
    {
        int r = tid & 31, kg = tid >> 5;          // kg: 16-k chunk
        int gi = 0; bool act = (r < ni);
        if (act) gi = g_sorted[start + i0 + r];
        const float4* src = (const float4*)&g_fx[(size_t)gi*ZD + kg*16];
        #pragma unroll
        for (int q = 0; q < 4; q++){
            float4 v = act ? src[q] : make_float4(0.f,0.f,0.f,0.f);
            int kb = kg*16 + q*4;
            FxsTd[(kb+0)*68 + 2*r] = v.x; FxsTd[(kb+0)*68 + 2*r + 1] = v.x;
            FxsTd[(kb+1)*68 + 2*r] = v.y; FxsTd[(kb+1)*68 + 2*r + 1] = v.y;
            FxsTd[(kb+2)*68 + 2*r] = v.z; FxsTd[(kb+2)*68 + 2*r + 1] = v.z;
            FxsTd[(kb+3)*68 + 2*r] = v.w; FxsTd[(kb+3)*68 + 2*r + 1] = v.w;
        }
    }

    const float* Wc = Ws + (size_t)cat*ZD*ZD;
    float4 pw[4];
    #pragma unroll
    for (int i = 0; i < 4; i++){
        int q = tid + 256*i;
        pw[i] = *(const float4*)&Wc[(size_t)(q >> 5)*ZD + (q & 31)*4];
    }
    // prefetch first 64-row Fs tile (gathered)
    float4 pf[8];
    {
        int nj0 = min(64, cnt);
        #pragma unroll
        for (int i = 0; i < 8; i++){
            int q = tid + 256*i;                   // 2048 slots: 64 rows x 32 float4
            int r = q >> 5;
            pf[i] = make_float4(0.f,0.f,0.f,0.f);
            if (r < nj0){
                int gj = g_sorted[start + r];
                pf[i] = *(const float4*)&g_fz[(size_t)gj*ZD + (q & 31)*4];
            }
        }
    }

    int r0 = (tid >> 5) * 4;     // warp-uniform row group
    int c0 = (tid & 31) * 4;
    u64 acc2[4][2] = {};         // [row][colpair]

    for (int kt = 0; kt < ZD; kt += 32){
        __syncthreads();                          // FxsTd staged (1st) / Wst consumers done
        #pragma unroll
        for (int i = 0; i < 4; i++){
            int q = tid + 256*i;
            *(float4*)&Wst[(q >> 5)*132 + (q & 31)*4] = pw[i];
        }
        __syncthreads();
        if (kt < ZD - 32){
            #pragma unroll
            for (int i = 0; i < 4; i++){
                int q = tid + 256*i;
                pw[i] = *(const float4*)&Wc[(size_t)(kt + 32 + (q >> 5))*ZD + (q & 31)*4];
            }
        }
        #pragma unroll
        for (int k = 0; k < 32; k++){
            const float* ap = &FxsTd[(kt+k)*68 + 2*r0];
            ulonglong2 a01 = *(const ulonglong2*)ap;        // dup(r0), dup(r0+1)
            ulonglong2 a23 = *(const ulonglong2*)(ap + 4);  // dup(r0+2), dup(r0+3)
            ulonglong2 bb  = *(const ulonglong2*)&Wst[k*132 + c0];  // colpairs
            fma2(acc2[0][0], a01.x, bb.x); fma2(acc2[0][1], a01.x, bb.y);
            fma2(acc2[1][0], a01.y, bb.x); fma2(acc2[1][1], a01.y, bb.y);
            fma2(acc2[2][0], a23.x, bb.x); fma2(acc2[2][1], a23.x, bb.y);
            fma2(acc2[3][0], a23.y, bb.x); fma2(acc2[3][1], a23.y, bb.y);
        }
    }
    __syncthreads();             // phase-1 reads done; safe to overwrite

    // write U tile: acc[row] pairs are (c0,c0+1),(c0+2,c0+3) -> direct float4
    #pragma unroll
    for (int i = 0; i < 4; i++){
        float2 p0 = unpk(acc2[i][0]);
        float2 p1 = unpk(acc2[i][1]);
        *(float4*)&Us[(r0+i)*128 + c0] = make_float4(p0.x, p0.y, p1.x, p1.y);
    }

    // phase 2: 64-wide j-tiles; lane jj handles j = j0+jj and j0+32+jj
    int jj = tid & 31;
    int ig = tid >> 5;           // warp owns rows ig*4..+3
    float sum[4] = {0.f, 0.f, 0.f, 0.f};
    int nt64 = (cnt + 63) >> 6;

    for (int jt = 0; jt < nt64; jt++){
        int j0 = jt*64;
        int nj = min(64, cnt - j0);
        __syncthreads();         // Us visible (1st) / Fs consumers done
        #pragma unroll
        for (int i = 0; i < 8; i++){
            int q = tid + 256*i;
            *(float4*)&Fs[(q >> 5)*132 + (q & 31)*4] = pf[i];
        }
        __syncthreads();
        if (jt + 1 < nt64){
            int j0n = j0 + 64;
            int njn = min(64, cnt - j0n);
            #pragma unroll
            for (int i = 0; i < 8; i++){
                int q = tid + 256*i;
                int r = q >> 5;
                pf[i] = make_float4(0.f,0.f,0.f,0.f);
                if (r < njn){
                    int gj = g_sorted[start + j0n + r];
                    pf[i] = *(const float4*)&g_fz[(size_t)gj*ZD + (q & 31)*4];
                }
            }
        }

        u64 a1[4] = {}, a2[4] = {};
        #pragma unroll
        for (int k0 = 0; k0 < ZD; k0 += 4){
            ulonglong2 f1 = *(const ulonglong2*)&Fs[jj*132 + k0];
            ulonglong2 f2 = *(const ulonglong2*)&Fs[(jj+32)*132 + k0];
            #pragma unroll
            for (int m = 0; m < 4; m++){
                ulonglong2 u = *(const ulonglong2*)&Us[(ig*4 + m)*128 + k0]; // bcast
                fma2(a1[m], u.x, f1.x); fma2(a1[m], u.y, f1.y);
                fma2(a2[m], u.x, f2.x); fma2(a2[m], u.y, f2.y);
            }
        }
        #pragma unroll
        for (int m = 0; m < 4; m++){
            float2 s1 = unpk(a1[m]); float d1 = s1.x + s1.y;
            float2 s2 = unpk(a2[m]); float d2 = s2.x + s2.y;
            int rr = ig*4 + m;
            int gd = i0 + rr;                      // diagonal j within category
            if (rr < ni && gd >= j0 && gd < j0 + 64 && (gd & 31) == jj)
                Ts[rr] = softplusf(((gd - j0) >> 5) ? d2 : d1);
            float v = 0.f;
            if (jj      < nj) v += softplusf(d1);
            if (jj + 32 < nj) v += softplusf(d2);
            v += __shfl_xor_sync(0xffffffffu, v, 16);
            v += __shfl_xor_sync(0xffffffffu, v, 8);
            v += __shfl_xor_sync(0xffffffffu, v, 4);
            v += __shfl_xor_sync(0xffffffffu, v, 2);
            v += __shfl_xor_sync(0xffffffffu, v, 1);
            sum[m] += v;
        }
    }
    __syncthreads();             // Ts visible

    if (jj == 0){
        float inv = 1.f / (float)cnt;
        #pragma unroll
        for (int m = 0; m < 4; m++){
            int rr = ig*4 + m;
            if (rr < ni)
                out[gidx[rr]] = logf(Ts[rr] + EPSV) - logf(sum[m]*inv + EPSV);
        }
    }
}

// ---------------- launch ----------------------------------------------------
extern "C" void kernel_launch(void* const* d_in, const int* in_sizes, int n_in,
                              void* d_out, int out_size){
    const float* x  = (const float*)d_in[0];
    const int*   c  = (const int*)  d_in[1];
    const float* z  = (const float*)d_in[2];
    const float* W1 = (const float*)d_in[3];
    const float* b1 = (const float*)d_in[4];
    const float* W2 = (const float*)d_in[5];
    const float* b2 = (const float*)d_in[6];
    const float* Wz = (const float*)d_in[7];
    const float* bz = (const float*)d_in[8];
    const float* Ws = (const float*)d_in[9];
    float* out = (float*)d_out;

    cudaFuncSetAttribute(uneg_kernel, cudaFuncAttributeMaxDynamicSharedMemorySize,
                         UNEG_SMEM_BYTES);

    prep_kernel <<<1 + NFX + NFZ, 256>>>(x, W1, b1, W2, b2, z, Wz, bz, c);
    uneg_kernel <<<NWORK_MAX, 256, UNEG_SMEM_BYTES>>>(Ws, out);
}